// round 14
// baseline (speedup 1.0000x reference)
#include <cuda_runtime.h>
#include <cstdint>
#include <math.h>

#define HID   128
#define G4    512
#define OUTC  7
#define LEN   2048
#define BATCH 10
#define CL    2     // CTAs per cluster
#define NB    5     // batch elements interleaved per cluster
#define TPB   288   // 8 matvec warps (256 gate rows) + 1 control warp

// Packed fp32x2 FMA (Blackwell): 2 fp32 FMAs per lane per issue.
#define FMA2(d,a,b,c) asm("fma.rn.f32x2 %0, %1, %2, %3;" : "=l"(d) : "l"(a), "l"(b), "l"(c))

__device__ __forceinline__ unsigned smem_u32(const void* p) {
    return (unsigned)__cvta_generic_to_shared(p);
}
__device__ __forceinline__ unsigned my_ctarank() {
    unsigned r; asm("mov.u32 %0, %%cluster_ctarank;" : "=r"(r)); return r;
}
__device__ __forceinline__ unsigned mapa_u32(unsigned a, unsigned r) {
    unsigned o; asm("mapa.shared::cluster.u32 %0, %1, %2;" : "=r"(o) : "r"(a), "r"(r)); return o;
}
#define CLUSTER_SYNC() do { \
    asm volatile("barrier.cluster.arrive.aligned;" ::: "memory"); \
    asm volatile("barrier.cluster.wait.aligned;"   ::: "memory"); \
} while (0)

#define MBAR_WAIT_CL(addr, parity) do {                                          \
    unsigned _done;                                                              \
    do {                                                                         \
        asm volatile("{\n\t.reg .pred p;\n\t"                                    \
            "mbarrier.try_wait.parity.acquire.cluster.shared::cta.b64 p, [%1], %2, 0x989680;\n\t" \
            "selp.b32 %0, 1, 0, p;\n\t}"                                         \
            : "=r"(_done) : "r"(addr), "r"(parity) : "memory");                  \
    } while (!_done);                                                            \
} while (0)

// HW tanh (MUFU.TANH): validated R10 at rel_err 2.2e-6 end-to-end.
__device__ __forceinline__ float htanh(float x) {
    float y; asm("tanh.approx.f32 %0, %1;" : "=f"(y) : "f"(x)); return y;
}
__device__ __forceinline__ float hsig(float x) {
    return fmaf(0.5f, htanh(0.5f * x), 0.5f);
}

// 16 FMA2 pairs over one 64-wide half of h. W0 in {0,32}, H0 in {0,64}.
#define DOT_HALF(W0, H0) do {                                             \
    const float* hh = hb + (H0);                                          \
    _Pragma("unroll")                                                     \
    for (int q = 0; q < 16; q++) {                                        \
        ulonglong2 hv = *reinterpret_cast<const ulonglong2*>(hh + 4 * q); \
        FMA2(a0, w[(W0) + 2 * q],     hv.x, a0);                          \
        FMA2(a1, w[(W0) + 2 * q + 1], hv.y, a1);                          \
    } } while (0)

// LATENCY-HIDING BY BATCH INTERLEAVE. 2-CTA cluster runs NB=5 independent
// batch recurrences; W_hh register tiles are shared across batches, so each
// iteration executes step t of all 5 batches back-to-back. While batch b's
// DSMEM h-exchange + mbarrier round trip is in flight, batches b+1.. compute.
// Per-batch protocol identical to R8 (passed): unit-partitioned (CTA r owns
// units [64r,64r+64)), warp-local cell via 3 shuffles, ping-pong mbarriers
// (count 64), early-sidx publish, one __syncthreads per iteration.
__global__ void __cluster_dims__(CL,1,1) __launch_bounds__(TPB, 1)
lstm_decode_kernel(const float* __restrict__ h0,      const float* __restrict__ c0,
                   const float* __restrict__ tgt_oh,  const unsigned* __restrict__ tf_mask,
                   const float* __restrict__ W_ih,    const float* __restrict__ W_hh,
                   const float* __restrict__ b_ih,    const float* __restrict__ b_hh,
                   const float* __restrict__ W_out,   const float* __restrict__ b_out,
                   float* __restrict__ out)
{
    __shared__ __align__(16) float h_sm[NB][3][HID]; // triple-buffered h per batch
    __shared__ float wih_t[OUTC * G4];               // W_ih transposed [c][row]
    __shared__ float wout_sm[OUTC * HID];
    __shared__ float bout_sm[OUTC];
    __shared__ __align__(8) unsigned long long mbar[NB * 2]; // ping-pong per batch
    __shared__ unsigned sidx_word[NB];               // (tag<<3)|sidx per batch
    __shared__ short tfidx_sm[LEN];                  // batch-independent

    const int      tid  = threadIdx.x;
    const unsigned rank = my_ctarank();
    const unsigned peer = rank ^ 1u;
    const int      cid  = blockIdx.x / CL;           // cluster id 0..1
    const bool     mv   = tid < 256;
    const int      wi   = tid >> 5;                  // warp 0..8
    const int      l    = tid & 31;
    const int      ui   = l & 7;                     // unit-in-warp
    const int      qg   = l >> 3;                    // gate 0..3 (i,f,g,o)
    const int      uu   = (int)rank * 64 + wi * 8 + ui;  // owned unit (mv only)
    const int      row  = qg * HID + uu;             // owned gate row

    // --- one-time setup -----------------------------------------------------
    unsigned long long w[64];                        // 128 W_hh weights, f32x2
    float bias = 0.0f, c[NB];
    float wout_reg[28];                              // control: W_out by lane
    #pragma unroll
    for (int b = 0; b < NB; b++) c[b] = 0.0f;
    if (mv) {
        const unsigned long long* wr = (const unsigned long long*)(W_hh + (size_t)row * HID);
        #pragma unroll
        for (int k = 0; k < 64; k++) w[k] = wr[k];
        bias = b_ih[row] + b_hh[row];
        if (l < 8) {
            #pragma unroll
            for (int b = 0; b < NB; b++) c[b] = c0[(cid * NB + b) * HID + uu];
        }
    }
    for (int i = tid; i < OUTC * G4; i += TPB) {     // transpose W_ih
        int cc = i >> 9, r0 = i & 511;
        wih_t[i] = W_ih[r0 * OUTC + cc];
    }
    for (int i = tid; i < OUTC * HID; i += TPB) wout_sm[i] = W_out[i];
    if (tid < OUTC) bout_sm[tid] = b_out[tid];
    if (tid < HID) {
        #pragma unroll
        for (int b = 0; b < NB; b++)
            h_sm[b][0][tid] = h0[(cid * NB + b) * HID + tid];
    }
    if (tid == 0) {
        #pragma unroll
        for (int b = 0; b < NB; b++) {
            sidx_word[b] = (unsigned)(OUTC - 1);     // tag 0, x0 one-hot OUT-1
            asm volatile("mbarrier.init.shared.b64 [%0], %1;"
                         :: "r"(smem_u32(&mbar[b * 2])),     "r"(64u) : "memory");
            asm volatile("mbarrier.init.shared.b64 [%0], %1;"
                         :: "r"(smem_u32(&mbar[b * 2 + 1])), "r"(64u) : "memory");
        }
    }
    for (int t = tid; t < LEN; t += TPB) {           // teacher-forcing indices
        short v = -1;
        if (tf_mask[t] != 0u) {
            v = 0;
            #pragma unroll
            for (int k = 0; k < OUTC; k++)
                if (tgt_oh[(t + 1) * OUTC + k] > 0.5f) v = (short)k;
        }
        tfidx_sm[t] = v;
    }
    __syncthreads();
    if (!mv) {                                       // control: W_out into regs
        #pragma unroll
        for (int k = 0; k < OUTC; k++)
            #pragma unroll
            for (int q = 0; q < 4; q++)
                wout_reg[k * 4 + q] = wout_sm[k * HID + l + 32 * q];
    }
    CLUSTER_SYNC();   // smem/mbar init visible cluster-wide before remote ops

    const unsigned mb_l0 = smem_u32(&mbar[0]);
    const unsigned mb_r0 = mapa_u32(mb_l0, peer);
    const unsigned h_r0  = mapa_u32(smem_u32(&h_sm[0][0][0]), peer);
    volatile unsigned* sw = sidx_word;

    int cur3 = 0, nxt3 = 1;                          // shared rotation, all batches

    // --- time loop: iter t = step t (matvec/cell) + step t-1 (control), x NB
    for (int t = 0; t <= LEN; t++) {
        for (int b = 0; b < NB; b++) {
            // wait for peer's step t-1 h exchange of batch b
            if (t > 0) {
                MBAR_WAIT_CL(mb_l0 + ((b * 2 + ((t - 1) & 1)) << 3), ((t - 1) >> 1) & 1);
            }
            const float* hb = h_sm[b][cur3];

            float p = 0.0f;
            if (mv && t < LEN) {
                unsigned long long a0 = 0ull, a1 = 0ull;
                DOT_HALF(0, 0);
                DOT_HALF(32, 64);
                float2 f0 = *reinterpret_cast<float2*>(&a0);
                float2 f1 = *reinterpret_cast<float2*>(&a1);
                p = (f0.x + f0.y) + (f1.x + f1.y);
            }
            if (!mv && t > 0) {                      // control: batch b, step t-1
                float hj[4];
                #pragma unroll
                for (int q = 0; q < 4; q++) hj[q] = hb[l + 32 * q];
                float pk[OUTC];
                #pragma unroll
                for (int k = 0; k < OUTC; k++) {
                    float s = 0.0f;
                    #pragma unroll
                    for (int q = 0; q < 4; q++) s = fmaf(hj[q], wout_reg[k * 4 + q], s);
                    #pragma unroll
                    for (int off = 16; off; off >>= 1)
                        s += __shfl_xor_sync(0xffffffffu, s, off);
                    pk[k] = s;
                }
                float lv = -3.4e38f;
                if (l < OUTC) {
                    float v = pk[0];
                    if (l == 1) v = pk[1];
                    if (l == 2) v = pk[2];
                    if (l == 3) v = pk[3];
                    if (l == 4) v = pk[4];
                    if (l == 5) v = pk[5];
                    if (l == 6) v = pk[6];
                    lv = v + bout_sm[l];
                }
                float m = lv; int ai = (l < OUTC) ? l : 1000;
                #pragma unroll
                for (int off = 16; off; off >>= 1) {
                    float om = __shfl_xor_sync(0xffffffffu, m, off);
                    int   oi = __shfl_xor_sync(0xffffffffu, ai, off);
                    if (om > m || (om == m && oi < ai)) { m = om; ai = oi; }
                }
                if (l == 0) {                        // publish sidx EARLY
                    int tv = tfidx_sm[t - 1];
                    int si = (tv >= 0) ? tv : ai;
                    sw[b] = ((unsigned)t << 3) | (unsigned)si;
                }
                float e = (l < OUTC) ? __expf(lv - m) : 0.0f;
                float s2 = e;
                #pragma unroll
                for (int off = 16; off; off >>= 1) s2 += __shfl_xor_sync(0xffffffffu, s2, off);
                if (l < OUTC && rank == 0) {
                    float lg = __logf(s2);
                    out[(((size_t)(cid * NB + b)) * LEN + (t - 1)) * OUTC + l] = lv - m - lg;
                }
            }

            // gate + activation + in-warp cell + peer exchange (batch b)
            if (mv && t < LEN) {
                unsigned v;                          // spin for sidx tag == t
                do { v = sw[b]; } while ((v >> 3) != (unsigned)t);
                float gv = p + bias + wih_t[(v & 7u) * G4 + row];   // x one-hot
                float a  = (qg == 2) ? htanh(gv) : hsig(gv);
                float aF = __shfl_sync(0xffffffffu, a, ui + 8);
                float aG = __shfl_sync(0xffffffffu, a, ui + 16);
                float aO = __shfl_sync(0xffffffffu, a, ui + 24);
                if (l < 8) {                         // lane owns unit uu
                    float c2 = aF * c[b] + a * aG;   // a == aI here
                    float h2 = aO * htanh(c2);
                    c[b] = c2;
                    h_sm[b][nxt3][uu] = h2;
                    unsigned hr = h_r0 + (unsigned)(((b * 3 + nxt3) * HID + uu) * 4);
                    asm volatile("st.shared::cluster.f32 [%0], %1;" :: "r"(hr), "f"(h2) : "memory");
                    asm volatile("mbarrier.arrive.release.cluster.shared::cluster.b64 _, [%0];"
                                 :: "r"(mb_r0 + ((b * 2 + (t & 1)) << 3)) : "memory");
                }
            }
        }
        __syncthreads();   // one bar per iteration (NB steps)

        cur3 = nxt3; nxt3 = (nxt3 == 2) ? 0 : nxt3 + 1;
    }

    // final states: h(LEN-1) lives in buffer LEN%3; c in registers of lanes 0-7
    if (mv && l < 8) {
        #pragma unroll
        for (int b = 0; b < NB; b++) {
            const int bg = cid * NB + b;
            out[(size_t)BATCH * LEN * OUTC + bg * HID + uu]               = h_sm[b][LEN % 3][uu];
            out[(size_t)BATCH * LEN * OUTC + BATCH * HID + bg * HID + uu] = c[b];
        }
    }
    CLUSTER_SYNC();   // keep smem alive until peer's last remote ops land
}

extern "C" void kernel_launch(void* const* d_in, const int* in_sizes, int n_in,
                              void* d_out, int out_size)
{
    (void)in_sizes; (void)n_in; (void)out_size;
    lstm_decode_kernel<<<(BATCH / NB) * CL, TPB>>>(
        (const float*)d_in[0], (const float*)d_in[1], (const float*)d_in[2],
        (const unsigned*)d_in[3], (const float*)d_in[4], (const float*)d_in[5],
        (const float*)d_in[6], (const float*)d_in[7], (const float*)d_in[8],
        (const float*)d_in[9], (float*)d_out);
}

// round 17
// speedup vs baseline: 5.9408x; 5.9408x over previous
#include <cuda_runtime.h>
#include <cstdint>
#include <math.h>

#define HID   128
#define G4    512
#define OUTC  7
#define LEN   2048
#define BATCH 10
#define TPB   288   // 8 matvec warps (256 gate rows) + 1 control warp

// Packed fp32x2 FMA (Blackwell): 2 fp32 FMAs per lane per issue.
#define FMA2(d,a,b,c) asm("fma.rn.f32x2 %0, %1, %2, %3;" : "=l"(d) : "l"(a), "l"(b), "l"(c))

__device__ __forceinline__ unsigned smem_u32(const void* p) {
    return (unsigned)__cvta_generic_to_shared(p);
}
__device__ __forceinline__ unsigned my_ctarank() {
    unsigned r; asm("mov.u32 %0, %%cluster_ctarank;" : "=r"(r)); return r;
}
__device__ __forceinline__ unsigned mapa_u32(unsigned a, unsigned r) {
    unsigned o; asm("mapa.shared::cluster.u32 %0, %1, %2;" : "=r"(o) : "r"(a), "r"(r)); return o;
}
#define CLUSTER_SYNC() do { \
    asm volatile("barrier.cluster.arrive.aligned;" ::: "memory"); \
    asm volatile("barrier.cluster.wait.aligned;"   ::: "memory"); \
} while (0)

#define MBAR_WAIT_CL(addr, parity) do {                                          \
    unsigned _done;                                                              \
    do {                                                                         \
        asm volatile("{\n\t.reg .pred p;\n\t"                                    \
            "mbarrier.try_wait.parity.acquire.cluster.shared::cta.b64 p, [%1], %2, 0x989680;\n\t" \
            "selp.b32 %0, 1, 0, p;\n\t}"                                         \
            : "=r"(_done) : "r"(addr), "r"(parity) : "memory");                  \
    } while (!_done);                                                            \
} while (0)

// HW tanh (MUFU.TANH): validated at rel_err 2.2e-6 end-to-end (R10/R12).
__device__ __forceinline__ float htanh(float x) {
    float y; asm("tanh.approx.f32 %0, %1;" : "=f"(y) : "f"(x)); return y;
}
__device__ __forceinline__ float hsig(float x) {
    return fmaf(0.5f, htanh(0.5f * x), 0.5f);
}

// 16 FMA2 pairs over one 64-wide half of h. W0 in {0,32}, H0 in {0,64}.
#define DOT_HALF(W0, H0) do {                                             \
    const float* hh = hb + (H0);                                          \
    _Pragma("unroll")                                                     \
    for (int q = 0; q < 16; q++) {                                        \
        ulonglong2 hv = *reinterpret_cast<const ulonglong2*>(hh + 4 * q); \
        FMA2(a0, w[(W0) + 2 * q],     hv.x, a0);                          \
        FMA2(a1, w[(W0) + 2 * q + 1], hv.y, a1);                          \
    } } while (0)

// WARP-AUTONOMOUS DATAFLOW. 2-CTA cluster per batch, unit-partitioned (CTA r
// owns units [64r,64r+64)). NO __syncthreads in the time loop: per-step events
// are split into LOCAL (count 64, plain arrive) and REMOTE (count 64,
// release.cluster arrive) ping-pong mbarriers. Consumers wait local-event,
// compute the local-half work, then wait remote-event — hiding the ~200-cyc
// DSMEM propagation under local compute. Control warp: 28 lanes = 7 logits x 4
// chunks with register weights, publishes sidx before softmax. Warp skew is
// bounded by the sidx-tag gating + triple-buffered h.
__global__ void __cluster_dims__(2,1,1) __launch_bounds__(TPB, 1)
lstm_decode_kernel(const float* __restrict__ h0,      const float* __restrict__ c0,
                   const float* __restrict__ tgt_oh,  const unsigned* __restrict__ tf_mask,
                   const float* __restrict__ W_ih,    const float* __restrict__ W_hh,
                   const float* __restrict__ b_ih,    const float* __restrict__ b_hh,
                   const float* __restrict__ W_out,   const float* __restrict__ b_out,
                   float* __restrict__ out)
{
    __shared__ __align__(16) float h_sm[3][HID];     // triple-buffered h (global unit idx)
    __shared__ float wih_t[OUTC * G4];               // W_ih transposed [c][row]
    __shared__ float bout_sm[OUTC];
    __shared__ float lsm[OUTC];
    __shared__ __align__(8) unsigned long long mbar[2][2];  // [pingpong][local,remote]
    __shared__ unsigned sidx_word;                   // (tag<<3)|sidx
    __shared__ short tfidx_sm[LEN];

    const int      tid  = threadIdx.x;
    const unsigned rank = my_ctarank();
    const unsigned peer = rank ^ 1u;
    const int      b    = blockIdx.x >> 1;
    const bool     mv   = tid < 256;
    const int      wi   = tid >> 5;                  // warp 0..8
    const int      l    = tid & 31;
    const int      ui   = l & 7;                     // unit-in-warp
    const int      qg   = l >> 3;                    // gate 0..3 (i,f,g,o)
    const int      uu   = (int)rank * 64 + wi * 8 + ui;  // owned unit (mv only)
    const int      row  = qg * HID + uu;             // owned gate row

    // --- one-time setup -----------------------------------------------------
    unsigned long long w[64];                        // 128 W_hh weights, f32x2
    float bias = 0.0f, c = 0.0f;
    float wout_reg[32];                              // control: W_out chunk of 32
    if (mv) {
        const unsigned long long* wr = (const unsigned long long*)(W_hh + (size_t)row * HID);
        #pragma unroll
        for (int k = 0; k < 64; k++) w[k] = wr[k];
        bias = b_ih[row] + b_hh[row];
        if (l < 8) c = c0[b * HID + uu];             // c kept in register
    } else if (l < 28) {                             // lane = k*4 + j
        const int k = l >> 2, j = l & 3;
        #pragma unroll
        for (int q = 0; q < 32; q++) wout_reg[q] = W_out[k * HID + j * 32 + q];
    }
    for (int i = tid; i < OUTC * G4; i += TPB) {     // transpose W_ih
        int cc = i >> 9, r0 = i & 511;
        wih_t[i] = W_ih[r0 * OUTC + cc];
    }
    if (tid < OUTC) bout_sm[tid] = b_out[tid];
    if (tid < HID) h_sm[0][tid] = h0[b * HID + tid];
    if (tid == 0) {
        sidx_word = (unsigned)(OUTC - 1);            // tag 0, x0 one-hot OUT-1
        #pragma unroll
        for (int pp = 0; pp < 2; pp++) {
            asm volatile("mbarrier.init.shared.b64 [%0], %1;"
                         :: "r"(smem_u32(&mbar[pp][0])), "r"(64u) : "memory");  // local
            asm volatile("mbarrier.init.shared.b64 [%0], %1;"
                         :: "r"(smem_u32(&mbar[pp][1])), "r"(64u) : "memory");  // remote
        }
    }
    for (int t = tid; t < LEN; t += TPB) {           // teacher-forcing indices
        short v = -1;
        if (tf_mask[t] != 0u) {
            v = 0;
            #pragma unroll
            for (int k = 0; k < OUTC; k++)
                if (tgt_oh[(t + 1) * OUTC + k] > 0.5f) v = (short)k;
        }
        tfidx_sm[t] = v;
    }
    __syncthreads();
    CLUSTER_SYNC();   // smem/mbar init visible cluster-wide before remote ops

    const unsigned mb00 = smem_u32(&mbar[0][0]);     // [pp][lr] stride 8
    const unsigned mbR  = mapa_u32(mb00, peer);      // peer's barrier array
    const unsigned h_r0 = mapa_u32(smem_u32(&h_sm[0][0]), peer);
    volatile unsigned* sw = &sidx_word;

    int cur3 = 0, nxt3 = 1;                          // read cur3, write nxt3

    // --- time loop (no __syncthreads inside) --------------------------------
    for (int t = 0; t <= LEN; t++) {
        const float* hb = h_sm[cur3];
        const unsigned wpp = (unsigned)((t - 1) & 1);       // event(t-1) barriers
        const unsigned wph = (unsigned)(((t - 1) >> 1) & 1);

        if (mv) {
            if (t < LEN) {
                unsigned long long a0 = 0ull, a1 = 0ull;
                // local-half dot (own CTA's h) after LOCAL event
                if (t > 0) MBAR_WAIT_CL(mb00 + (wpp << 4), wph);
                if (rank == 0) { DOT_HALF(0, 0);   } else { DOT_HALF(32, 64); }
                // remote-half dot after REMOTE event (propagation hidden above)
                if (t > 0) MBAR_WAIT_CL(mb00 + (wpp << 4) + 8, wph);
                if (rank == 0) { DOT_HALF(32, 64); } else { DOT_HALF(0, 0); }
                float2 f0 = *reinterpret_cast<float2*>(&a0);
                float2 f1 = *reinterpret_cast<float2*>(&a1);
                float p = (f0.x + f0.y) + (f1.x + f1.y);

                unsigned v;                          // spin for sidx tag == t
                do { v = *sw; } while ((v >> 3) != (unsigned)t);
                float gv = p + bias + wih_t[(v & 7u) * G4 + row];   // x one-hot
                float a  = (qg == 2) ? htanh(gv) : hsig(gv);
                float aF = __shfl_sync(0xffffffffu, a, ui + 8);
                float aG = __shfl_sync(0xffffffffu, a, ui + 16);
                float aO = __shfl_sync(0xffffffffu, a, ui + 24);
                if (l < 8) {                         // lane owns unit uu
                    float c2 = aF * c + a * aG;      // a == aI here
                    float h2 = aO * htanh(c2);
                    c = c2;
                    h_sm[nxt3][uu] = h2;             // local publish
                    unsigned hr = h_r0 + (unsigned)((nxt3 * HID + uu) * 4);
                    asm volatile("st.shared::cluster.f32 [%0], %1;" :: "r"(hr), "f"(h2) : "memory");
                    const unsigned app = (unsigned)(t & 1);
                    // local arrive (orders local STS, cta release)
                    asm volatile("mbarrier.arrive.shared.b64 _, [%0];"
                                 :: "r"(mb00 + (app << 4)) : "memory");
                    // remote arrive on peer's REMOTE barrier (orders DSMEM store)
                    asm volatile("mbarrier.arrive.release.cluster.shared::cluster.b64 _, [%0];"
                                 :: "r"(mbR + (app << 4) + 8) : "memory");
                }
            }
        } else if (t > 0) {
            // ---- control warp: scan-step t-1 (h2(t-1) == h(t) == event t-1) --
            const int k = l >> 2, j = l & 3;         // logit k, chunk j (32 h)
            const bool valid  = (l < 28);
            const bool jlocal = (((unsigned)(l >> 1) & 1u) == rank);  // j>>1==rank
            float s0 = 0.f, s1 = 0.f, s2 = 0.f, s3 = 0.f;
            MBAR_WAIT_CL(mb00 + (wpp << 4), wph);            // LOCAL event
            if (valid && jlocal) {
                const float4* hv4 = (const float4*)(hb + j * 32);
                #pragma unroll
                for (int q = 0; q < 8; q++) {
                    float4 hv = hv4[q];
                    s0 = fmaf(hv.x, wout_reg[q * 4 + 0], s0);
                    s1 = fmaf(hv.y, wout_reg[q * 4 + 1], s1);
                    s2 = fmaf(hv.z, wout_reg[q * 4 + 2], s2);
                    s3 = fmaf(hv.w, wout_reg[q * 4 + 3], s3);
                }
            }
            MBAR_WAIT_CL(mb00 + (wpp << 4) + 8, wph);        // REMOTE event
            if (valid && !jlocal) {
                const float4* hv4 = (const float4*)(hb + j * 32);
                #pragma unroll
                for (int q = 0; q < 8; q++) {
                    float4 hv = hv4[q];
                    s0 = fmaf(hv.x, wout_reg[q * 4 + 0], s0);
                    s1 = fmaf(hv.y, wout_reg[q * 4 + 1], s1);
                    s2 = fmaf(hv.z, wout_reg[q * 4 + 2], s2);
                    s3 = fmaf(hv.w, wout_reg[q * 4 + 3], s3);
                }
            }
            float s = (s0 + s1) + (s2 + s3);
            s += __shfl_xor_sync(0xffffffffu, s, 1);
            s += __shfl_xor_sync(0xffffffffu, s, 2);         // group-of-4 sum
            if (valid && j == 0) lsm[k] = s + bout_sm[k];    // lanes 0,4,..,24
            // same-warp STS -> LDS is program-ordered
            float lv = (l < OUTC) ? lsm[l] : -3.4e38f;
            float m = lv; int ai = (l < OUTC) ? l : 1000;
            #pragma unroll
            for (int off = 1; off <= 4; off <<= 1) {         // reduce lanes 0..7
                float om = __shfl_xor_sync(0xffffffffu, m, off);
                int   oi = __shfl_xor_sync(0xffffffffu, ai, off);
                if (om > m || (om == m && oi < ai)) { m = om; ai = oi; }
            }
            if (l == 0) {                            // publish sidx EARLY
                int tv = tfidx_sm[t - 1];
                int si = (tv >= 0) ? tv : ai;
                *sw = ((unsigned)t << 3) | (unsigned)si;
            }
            // softmax + STG off the critical path
            float e = (l < OUTC) ? __expf(lv - m) : 0.0f;
            float s2r = e;
            #pragma unroll
            for (int off = 1; off <= 4; off <<= 1)
                s2r += __shfl_xor_sync(0xffffffffu, s2r, off);
            if (l < OUTC && rank == 0) {
                float lg = __logf(s2r);
                out[((size_t)b * LEN + (t - 1)) * OUTC + l] = lv - m - lg;
            }
        }

        cur3 = nxt3; nxt3 = (nxt3 == 2) ? 0 : nxt3 + 1;
    }

    __syncthreads();   // all warps done before finals
    // final states: h(LEN-1) lives in buffer LEN%3; c in registers of lanes 0-7
    if (mv && l < 8) {
        out[(size_t)BATCH * LEN * OUTC + b * HID + uu]               = h_sm[LEN % 3][uu];
        out[(size_t)BATCH * LEN * OUTC + BATCH * HID + b * HID + uu] = c;
    }
    CLUSTER_SYNC();   // keep smem alive until peer's last remote ops land
}

extern "C" void kernel_launch(void* const* d_in, const int* in_sizes, int n_in,
                              void* d_out, int out_size)
{
    (void)in_sizes; (void)n_in; (void)out_size;
    lstm_decode_kernel<<<BATCH * 2, TPB>>>(
        (const float*)d_in[0], (const float*)d_in[1], (const float*)d_in[2],
        (const unsigned*)d_in[3], (const float*)d_in[4], (const float*)d_in[5],
        (const float*)d_in[6], (const float*)d_in[7], (const float*)d_in[8],
        (const float*)d_in[9], (float*)d_out);
}